// round 8
// baseline (speedup 1.0000x reference)
#include <cuda_runtime.h>
#include <cstdint>

// GausSplatingHead: per-point 3D Gaussian covariance from (scale, quaternion).
// R8: fully TMA-shaped tile kernel.
//   - inputs:  two cp.async.bulk loads (scales 6KB, rots 8KB) per tile into
//              smem, completion via one mbarrier (expect_tx = 14336 B)
//   - compute: 2 points/thread from smem
//   - output:  staged in 12KB smem, one cp.async.bulk store per tile
// Goal: probe whether the steady-state 5.9 TB/s mixed-stream floor is
// sensitive to DRAM request shaping (bulk bursts vs per-warp LDGs).

#define TPB  256
#define TILE 512   // points per block

#define SCALES_BYTES (TILE * 3 * 4)   // 6144
#define ROTS_BYTES   (TILE * 4 * 4)   // 8192
#define IN_BYTES     (SCALES_BYTES + ROTS_BYTES)
#define OUT_BYTES    (TILE * 6 * 4)   // 12288

__device__ __forceinline__ uint32_t smem_u32(const void* p) {
    uint32_t a;
    asm("{ .reg .u64 t; cvta.to.shared.u64 t, %1; cvt.u32.u64 %0, t; }"
        : "=r"(a) : "l"(p));
    return a;
}

__device__ __forceinline__ void cov_from_q(
    float r, float x, float y, float z,
    float s0, float s1, float s2, float* o /*6*/)
{
    float n2 = r * r + x * x + y * y + z * z;
    // R(q/||q||) entries are quadratic in q: fold normalization into the
    // factor 2 -> ss = 2/||q||^2. Algebraically identical to the reference.
    float ss = __fdividef(2.0f, n2);

    float xx = x * x * ss, yy = y * y * ss, zz = z * z * ss;
    float xy = x * y * ss, xz = x * z * ss, yz = y * z * ss;
    float rx = r * x * ss, ry = r * y * ss, rz = r * z * ss;

    float R00 = 1.0f - yy - zz, R01 = xy - rz, R02 = xz + ry;
    float R10 = xy + rz, R11 = 1.0f - xx - zz, R12 = yz - rx;
    float R20 = xz - ry, R21 = yz + rx, R22 = 1.0f - xx - yy;

    float a = s0 * s0, b = s1 * s1, c = s2 * s2;

    o[0] = R00 * R00 * a + R01 * R01 * b + R02 * R02 * c;  // 00
    o[1] = R00 * R10 * a + R01 * R11 * b + R02 * R12 * c;  // 01
    o[2] = R00 * R20 * a + R01 * R21 * b + R02 * R22 * c;  // 02
    o[3] = R10 * R10 * a + R11 * R11 * b + R12 * R12 * c;  // 11
    o[4] = R10 * R20 * a + R11 * R21 * b + R12 * R22 * c;  // 12
    o[5] = R20 * R20 * a + R21 * R21 * b + R22 * R22 * c;  // 22
}

__global__ __launch_bounds__(TPB) void gs_cov_r8_kernel(
    const float* __restrict__ scales,    // [n*3]
    const float* __restrict__ rots,      // [n*4]
    float* __restrict__ out,             // [n*6]
    int n)
{
    __shared__ __align__(16) float s_scales[TILE * 3];   // 6 KB
    __shared__ __align__(16) float s_rots[TILE * 4];     // 8 KB
    __shared__ __align__(16) float s_out[TILE * 6];      // 12 KB
    __shared__ __align__(8)  uint64_t s_mbar;

    const int tid  = threadIdx.x;
    const int base = blockIdx.x * TILE;

    if (base + TILE <= n) {
        // ---- phase 0: init mbarrier, issue both bulk loads ----
        uint32_t mbar = smem_u32(&s_mbar);
        if (tid == 0) {
            asm volatile("mbarrier.init.shared.b64 [%0], 1;"
                         :: "r"(mbar) : "memory");
            asm volatile("fence.proxy.async.shared::cta;" ::: "memory");
            asm volatile("mbarrier.arrive.expect_tx.shared.b64 _, [%0], %1;"
                         :: "r"(mbar), "n"(IN_BYTES) : "memory");
            const float* gsc = scales + (size_t)base * 3;
            const float* grt = rots   + (size_t)base * 4;
            asm volatile(
                "cp.async.bulk.shared::cta.global.mbarrier::complete_tx::bytes"
                " [%0], [%1], %2, [%3];"
                :: "r"(smem_u32(s_scales)), "l"(gsc), "n"(SCALES_BYTES),
                   "r"(mbar) : "memory");
            asm volatile(
                "cp.async.bulk.shared::cta.global.mbarrier::complete_tx::bytes"
                " [%0], [%1], %2, [%3];"
                :: "r"(smem_u32(s_rots)), "l"(grt), "n"(ROTS_BYTES),
                   "r"(mbar) : "memory");
        }
        __syncthreads();   // mbarrier init visible to all waiters

        // ---- wait for input tile (phase 0) ----
        {
            uint32_t done;
            asm volatile(
                "{\n\t"
                ".reg .pred p;\n\t"
                "mbarrier.try_wait.parity.acquire.cta.shared::cta.b64 p, [%1], 0;\n\t"
                "selp.b32 %0, 1, 0, p;\n\t"
                "}" : "=r"(done) : "r"(mbar) : "memory");
            while (!done) {
                asm volatile(
                    "{\n\t"
                    ".reg .pred p;\n\t"
                    "mbarrier.try_wait.parity.acquire.cta.shared::cta.b64 p, [%1], 0, 0x989680;\n\t"
                    "selp.b32 %0, 1, 0, p;\n\t"
                    "}" : "=r"(done) : "r"(mbar) : "memory");
            }
        }

        // ---- compute 2 points from smem ----
        const float4* sr4 = (const float4*)s_rots;
        float4 q0 = sr4[tid];
        float4 q1 = sr4[TPB + tid];

        float o0[6], o1[6];
        cov_from_q(q0.x, q0.y, q0.z, q0.w,
                   s_scales[3 * tid + 0], s_scales[3 * tid + 1],
                   s_scales[3 * tid + 2], o0);
        {
            int p = TPB + tid;
            cov_from_q(q1.x, q1.y, q1.z, q1.w,
                       s_scales[3 * p + 0], s_scales[3 * p + 1],
                       s_scales[3 * p + 2], o1);
        }

        float2* so2 = (float2*)s_out;
        so2[3 * tid + 0]         = make_float2(o0[0], o0[1]);
        so2[3 * tid + 1]         = make_float2(o0[2], o0[3]);
        so2[3 * tid + 2]         = make_float2(o0[4], o0[5]);
        so2[3 * (TPB + tid) + 0] = make_float2(o1[0], o1[1]);
        so2[3 * (TPB + tid) + 1] = make_float2(o1[2], o1[3]);
        so2[3 * (TPB + tid) + 2] = make_float2(o1[4], o1[5]);
        __syncthreads();

        // ---- one TMA bulk store per tile ----
        if (tid == 0) {
            asm volatile("fence.proxy.async.shared::cta;" ::: "memory");
            const float* gdst = out + (size_t)base * 6;
            asm volatile(
                "cp.async.bulk.global.shared::cta.bulk_group [%0], [%1], %2;"
                :: "l"(gdst), "r"(smem_u32(s_out)), "n"(OUT_BYTES)
                : "memory");
            asm volatile("cp.async.bulk.commit_group;" ::: "memory");
            asm volatile("cp.async.bulk.wait_group.read 0;" ::: "memory");
        }
    } else {
        // ---- tail tile (rare): scalar global path ----
#pragma unroll
        for (int p = 0; p < 2; p++) {
            int i = base + p * TPB + tid;
            if (i < n) {
                float o[6];
                cov_from_q(rots[4 * i + 0], rots[4 * i + 1],
                           rots[4 * i + 2], rots[4 * i + 3],
                           scales[3 * i + 0], scales[3 * i + 1],
                           scales[3 * i + 2], o);
#pragma unroll
                for (int k = 0; k < 6; k++) out[6 * i + k] = o[k];
            }
        }
    }
}

extern "C" void kernel_launch(void* const* d_in, const int* in_sizes, int n_in,
                              void* d_out, int out_size)
{
    const float* scales = (const float*)d_in[0];   // [N,3]
    const float* rots   = (const float*)d_in[1];   // [N,4]
    float* out          = (float*)d_out;           // [N,6]

    int n = in_sizes[0] / 3;
    int blocks = (n + TILE - 1) / TILE;
    gs_cov_r8_kernel<<<blocks, TPB>>>(scales, rots, out, n);
}